// round 11
// baseline (speedup 1.0000x reference)
#include <cuda_runtime.h>
#include <math.h>

#define BATCH 8192
#define EXP   1024
#define RR    8
#define DIM   384
#define HID   64
#define NP    (BATCH*2)             // 16384 (b,k) pairs; also per-router region capacity
#define TILE  64
#define RT    (NP/TILE)             // 256 tiles per router region
#define NBLK  (RR*RT)               // 2048 blocks for xu/scores (most exit early)

typedef unsigned long long u64;

// ---------------- f32x2 helpers (sm_103a packed fp32: 2x FMA throughput) ----------------
__device__ __forceinline__ u64 pack2(float lo, float hi) {
    u64 r; asm("mov.b64 %0, {%1, %2};" : "=l"(r) : "f"(lo), "f"(hi)); return r;
}
__device__ __forceinline__ float2 unpack2(u64 v) {
    float2 f; asm("mov.b64 {%0, %1}, %2;" : "=f"(f.x), "=f"(f.y) : "l"(v)); return f;
}
__device__ __forceinline__ void fma2(u64& d, u64 a, u64 b) {
    asm("fma.rn.f32x2 %0, %1, %2, %0;" : "+l"(d) : "l"(a), "l"(b));
}

// ---------------- device scratch (zero-initialized at module load) ----------------
__device__ __align__(16) float g_probs[BATCH*RR];
__device__ int   g_top_idx[NP];
__device__ int   g_cnt[RR];                 // zeroed at end of every replay (and at load)
__device__ int   g_list_bk1[RR*NP];         // bk+1; 0 = sentinel (zero-init = all sentinel)
__device__ float g_list_gw[RR*NP];
__device__ __align__(16) float g_xu[RR*NP*HID];      // [region row][h]
__device__ __align__(16) float g_ev[RR*EXP*HID];     // [r][e][h]
__device__ __align__(16) float g_contrib[NP*EXP];    // UNSCALED exp(score)
__device__ float g_scale[NP];               // gate_weight / sum_exp

// ---------------- kernel: gate + direct scatter into per-router regions ----------------
__global__ __launch_bounds__(256) void k_gate(const float* __restrict__ x,
                                              const float* __restrict__ gw,
                                              const float* __restrict__ gb) {
    int w = threadIdx.x >> 5, lane = threadIdx.x & 31;
    int b = blockIdx.x * 8 + w;
    float acc[8];
#pragma unroll
    for (int r = 0; r < 8; r++) acc[r] = 0.f;
    const float* xr = x + b * DIM;
    for (int k = lane; k < DIM; k += 32) {
        float xv = xr[k];
        float4 a = *(const float4*)(gw + k * 8);
        float4 c = *(const float4*)(gw + k * 8 + 4);
        acc[0] = fmaf(xv, a.x, acc[0]); acc[1] = fmaf(xv, a.y, acc[1]);
        acc[2] = fmaf(xv, a.z, acc[2]); acc[3] = fmaf(xv, a.w, acc[3]);
        acc[4] = fmaf(xv, c.x, acc[4]); acc[5] = fmaf(xv, c.y, acc[5]);
        acc[6] = fmaf(xv, c.z, acc[6]); acc[7] = fmaf(xv, c.w, acc[7]);
    }
#pragma unroll
    for (int r = 0; r < 8; r++)
#pragma unroll
        for (int s = 16; s; s >>= 1) acc[r] += __shfl_xor_sync(0xffffffffu, acc[r], s);
    if (lane == 0) {
        float lg[8];
#pragma unroll
        for (int r = 0; r < 8; r++) lg[r] = acc[r] + gb[r];
        float m = lg[0];
#pragma unroll
        for (int r = 1; r < 8; r++) m = fmaxf(m, lg[r]);
        float s = 0.f, p[8];
#pragma unroll
        for (int r = 0; r < 8; r++) { p[r] = expf(lg[r] - m); s += p[r]; }
        float inv = 1.f / s;
#pragma unroll
        for (int r = 0; r < 8; r++) g_probs[b * 8 + r] = p[r] * inv;
        int i0 = 0;
#pragma unroll
        for (int r = 1; r < 8; r++) if (lg[r] > lg[i0]) i0 = r;
        int i1 = (i0 == 0) ? 1 : 0;
#pragma unroll
        for (int r = 0; r < 8; r++) if (r != i0 && r != i1 && lg[r] > lg[i1]) i1 = r;
        float e1 = expf(lg[i1] - lg[i0]);   // lg[i0] >= lg[i1]
        float d  = 1.f + e1;
        g_top_idx[b * 2 + 0] = i0;
        g_top_idx[b * 2 + 1] = i1;
        // direct scatter: position within router region via atomic ticket.
        // Order varies across replays but rows in a region share the router, so
        // every bk-keyed result is permutation-invariant -> deterministic output.
        int p0 = atomicAdd(&g_cnt[i0], 1);
        int p1 = atomicAdd(&g_cnt[i1], 1);
        g_list_bk1[i0 * NP + p0] = b * 2 + 0 + 1;
        g_list_gw [i0 * NP + p0] = 1.f / d;
        g_list_bk1[i1 * NP + p1] = b * 2 + 1 + 1;
        g_list_gw [i1 * NP + p1] = e1 / d;
    }
}

// ---------------- shared GEMM body for xu/ev: 64 rows x 64 hid, K=384, f32x2 over d ----
// warp w owns rows 8w..8w+7; lane owns hid pair {lane, lane+32}.
// s_w: u64-swizzled [h][d2]: slot = h*32 + (d2 ^ (h&31)).
// inner loop over d4: x via LDS.128 broadcast -> crossbar 128 == FFMA2 128 (balanced).
template<bool IS_XU>
__device__ __forceinline__ void proj_body(const float* __restrict__ src,
                                          const float* __restrict__ Wb,
                                          const float* __restrict__ bias,
                                          const int* s_bk, int base, int e0,
                                          float* s_in, u64* s_w,
                                          float* dst) {
    int t = threadIdx.x, w = t >> 5, lane = t & 31;
    u64 acc[8][2];
#pragma unroll
    for (int i = 0; i < 8; i++) { acc[i][0] = 0ull; acc[i][1] = 0ull; }
    for (int c = 0; c < 6; c++) {
        __syncthreads();
#pragma unroll
        for (int i = 0; i < 4; i++) {          // stage 64 rows x 64 d (natural)
            int f = t + 256 * i, row = f >> 4, d16 = f & 15;
            float4 v = make_float4(0.f, 0.f, 0.f, 0.f);
            if (IS_XU) {
                int bk1 = s_bk[row];
                if (bk1 > 0) v = *(const float4*)(src + ((bk1 - 1) >> 1) * DIM + c * 64 + d16 * 4);
            } else {
                v = *(const float4*)(src + (e0 + row) * DIM + c * 64 + d16 * 4);
            }
            *(float4*)&s_in[row * 64 + d16 * 4] = v;
        }
        float* sw = (float*)s_w;
#pragma unroll
        for (int i = 0; i < 4; i++) {          // stage weights: transpose + swizzle
            int f = t + 256 * i, d = f >> 4, h16 = f & 15;
            float4 v = *(const float4*)(Wb + (c * 64 + d) * HID + h16 * 4);
            int d2 = d >> 1, par = d & 1;
            float vv[4] = {v.x, v.y, v.z, v.w};
#pragma unroll
            for (int jj = 0; jj < 4; jj++) {
                int h = h16 * 4 + jj;
                sw[(h * 32 + (d2 ^ (h & 31))) * 2 + par] = vv[jj];
            }
        }
        __syncthreads();
#pragma unroll 2
        for (int d4 = 0; d4 < 16; d4++) {
            int d2a = 2 * d4;
            u64 w00 = s_w[lane * 32 + (d2a ^ lane)];
            u64 w01 = s_w[lane * 32 + ((d2a + 1) ^ lane)];
            u64 w10 = s_w[(lane + 32) * 32 + (d2a ^ lane)];
            u64 w11 = s_w[(lane + 32) * 32 + ((d2a + 1) ^ lane)];
#pragma unroll
            for (int i = 0; i < 8; i++) {
                ulonglong2 xv = *(const ulonglong2*)&s_in[(8 * w + i) * 64 + 4 * d4]; // bcast
                fma2(acc[i][0], xv.x, w00); fma2(acc[i][0], xv.y, w01);
                fma2(acc[i][1], xv.x, w10); fma2(acc[i][1], xv.y, w11);
            }
        }
    }
    float b0 = bias[lane], b1 = bias[lane + 32];
#pragma unroll
    for (int i = 0; i < 8; i++) {
        float2 p0 = unpack2(acc[i][0]), p1 = unpack2(acc[i][1]);
        float y0 = p0.x + p0.y + b0;
        float y1 = p1.x + p1.y + b1;
        float ss = y0 * y0 + y1 * y1;
#pragma unroll
        for (int s = 16; s; s >>= 1) ss += __shfl_xor_sync(0xffffffffu, ss, s);
        float inv = 1.f / fmaxf(sqrtf(ss), 1e-12f);
        int row = base + 8 * w + i;
        dst[row * HID + lane]      = y0 * inv;
        dst[row * HID + lane + 32] = y1 * inv;
    }
}

// ev projection: independent of gate -> first launch
__global__ __launch_bounds__(256) void k_ev(const float* __restrict__ re,
                                            const float* __restrict__ Vw,
                                            const float* __restrict__ Vb) {
    __shared__ float s_in[64 * 64];
    __shared__ u64   s_w[64 * 32];
    int r = blockIdx.x >> 4, e0 = (blockIdx.x & 15) * 64;  // 128 blocks
    proj_body<false>(re, Vw + r * DIM * HID, Vb + r * HID, 0, r * EXP + e0, e0,
                     s_in, s_w, g_ev);
}

// xu projection over fixed regions; early-exit on empty tiles
__global__ __launch_bounds__(256) void k_xu(const float* __restrict__ x,
                                            const float* __restrict__ Uw,
                                            const float* __restrict__ Ub) {
    __shared__ float s_in[64 * 64];
    __shared__ u64   s_w[64 * 32];
    __shared__ int   s_bk[64];
    int r = blockIdx.x >> 8, ti = blockIdx.x & 255;
    if (ti * TILE >= g_cnt[r]) return;
    int base = r * NP + ti * TILE;
    int t = threadIdx.x;
    if (t < 64) s_bk[t] = g_list_bk1[base + t];
    proj_body<true>(x, Uw + r * DIM * HID, Ub + r * HID, s_bk, base, 0, s_in, s_w, g_xu);
}

// ---------------- scores GEMM + exp + per-row sum (launch slot 4 -> ncu capture) ------
// 64-row tile x 1024 experts, 8 chunks of 128 experts. warp w: rows 8w..8w+7;
// lane covers experts {lane,+32,+64,+96}. kk-packed f32x2, XOR-swizzled ev (STS.128,
// half-swap on odd key), xu via LDS.128 broadcast. crossbar 3072 < FFMA2 4096 / chunk.
__global__ __launch_bounds__(256) void k_scores() {
    extern __shared__ u64 dyn[];
    u64*   s_ev = dyn;                      // 4096 u64 = 32 KB
    float* s_xu = (float*)(dyn + 4096);     // 16 KB
    __shared__ int   s_bk[64];
    __shared__ float s_gw[64];
    int r = blockIdx.x >> 8, ti = blockIdx.x & 255;
    if (ti * TILE >= g_cnt[r]) return;
    int base = r * NP + ti * TILE;
    int t = threadIdx.x, w = t >> 5, lane = t & 31;
    if (t < 64) { s_bk[t] = g_list_bk1[base + t]; s_gw[t] = g_list_gw[base + t]; }
#pragma unroll
    for (int i = 0; i < 4; i++)
        ((float4*)s_xu)[t + 256 * i] = ((const float4*)(g_xu + base * HID))[t + 256 * i];

    float rowsum[8];
#pragma unroll
    for (int i = 0; i < 8; i++) rowsum[i] = 0.f;

    const float* evb = g_ev + r * (EXP * HID);
    for (int c = 0; c < 8; c++) {
        __syncthreads();
#pragma unroll
        for (int i = 0; i < 8; i++) {       // stage 128 experts x 64 h, swizzled u128
            int f = t + 256 * i, e = f >> 4, k4 = f & 15;
            float4 v = *(const float4*)(evb + (c * 128 + e) * HID + k4 * 4);
            int s = e & 31;
            u64 lo = pack2(v.x, v.y), hi = pack2(v.z, v.w);
            int base128 = e * 32 + (((2 * k4) ^ s) & ~1);
            ulonglong2 val;
            val.x = (s & 1) ? hi : lo;
            val.y = (s & 1) ? lo : hi;
            *(ulonglong2*)&s_ev[base128] = val;
        }
        __syncthreads();
        u64 acc[8][4];
#pragma unroll
        for (int i = 0; i < 8; i++)
#pragma unroll
            for (int j = 0; j < 4; j++) acc[i][j] = 0ull;
#pragma unroll 2
        for (int kk4 = 0; kk4 < 16; kk4++) {
            int k2a = 2 * kk4;
            u64 ea[4], eb[4];
#pragma unroll
            for (int j = 0; j < 4; j++) {
                ea[j] = s_ev[(j * 32 + lane) * 32 + (k2a ^ lane)];
                eb[j] = s_ev[(j * 32 + lane) * 32 + ((k2a + 1) ^ lane)];
            }
#pragma unroll
            for (int i = 0; i < 8; i++) {
                ulonglong2 xv = *(const ulonglong2*)&s_xu[(8 * w + i) * 64 + 4 * kk4]; // bcast
#pragma unroll
                for (int j = 0; j < 4; j++) {
                    fma2(acc[i][j], xv.x, ea[j]);
                    fma2(acc[i][j], xv.y, eb[j]);
                }
            }
        }
#pragma unroll
        for (int i = 0; i < 8; i++) {
            int bk1 = s_bk[8 * w + i];
            float ex[4], loc = 0.f;
#pragma unroll
            for (int j = 0; j < 4; j++) {
                float2 p = unpack2(acc[i][j]);
                ex[j] = __expf(p.x + p.y);   // |score| <= 1 (unit vectors): no max pass
                loc += ex[j];
            }
            rowsum[i] += loc;
            if (bk1 > 0) {
                float* o = g_contrib + (bk1 - 1) * EXP + c * 128;
#pragma unroll
                for (int j = 0; j < 4; j++) o[j * 32 + lane] = ex[j];
            }
        }
    }
#pragma unroll
    for (int i = 0; i < 8; i++) {
        float s = rowsum[i];
#pragma unroll
        for (int st = 16; st; st >>= 1) s += __shfl_xor_sync(0xffffffffu, s, st);
        int row = 8 * w + i;
        int bk1 = s_bk[row];
        if (lane == 0 && bk1 > 0) g_scale[bk1 - 1] = s_gw[row] / s;
    }
}

// ---------------- select (two-pass MLP inverse-CDF) + aux + counter reset -------------
__global__ __launch_bounds__(256) void k_select_aux(const float* __restrict__ rnd,
                                                    float* __restrict__ out) {
    __shared__ float sp[256][8];
    __shared__ float sm[256][8];
    int t = threadIdx.x;
    if (blockIdx.x == BATCH / 8) {          // aux block (+ reset g_cnt for next replay)
        float p[8], mk[8];
#pragma unroll
        for (int r = 0; r < 8; r++) { p[r] = 0.f; mk[r] = 0.f; }
        for (int b = t; b < BATCH; b += 256) {
#pragma unroll
            for (int r = 0; r < 8; r++) p[r] += g_probs[b * 8 + r];
            int i0 = g_top_idx[b * 2], i1 = g_top_idx[b * 2 + 1];
#pragma unroll
            for (int r = 0; r < 8; r++) mk[r] += (r == i0 ? 1.f : 0.f) + (r == i1 ? 1.f : 0.f);
        }
#pragma unroll
        for (int r = 0; r < 8; r++) { sp[t][r] = p[r]; sm[t][r] = mk[r]; }
        __syncthreads();
        for (int s = 128; s; s >>= 1) {
            if (t < s)
#pragma unroll
                for (int r = 0; r < 8; r++) { sp[t][r] += sp[t + s][r]; sm[t][r] += sm[t + s][r]; }
            __syncthreads();
        }
        if (t == 0) {
            float a = 0.f;
#pragma unroll
            for (int r = 0; r < 8; r++)
                a += (sp[0][r] / (float)BATCH) * (sm[0][r] / (float)BATCH);
            out[2 * BATCH] = 8.f * a * 0.05f;
        }
        if (t < RR) g_cnt[t] = 0;           // clean state for next replay
        return;
    }
    int w = t >> 5, lane = t & 31;
    int b = blockIdx.x * 8 + w;
    float rn = rnd[b];
    float s0 = g_scale[b * 2], s1 = g_scale[b * 2 + 1];
    const float4* c0 = (const float4*)(g_contrib + (b * 2) * EXP);
    const float4* c1 = c0 + EXP / 4;
    // pass 1: lane = 32-element chunk; all loads independent (high MLP)
    float loc = 0.f;
#pragma unroll
    for (int q = 0; q < 8; q++) {
        float4 a = c0[lane * 8 + q];
        float4 d = c1[lane * 8 + q];
        loc += fmaf(a.x, s0, d.x * s1) + fmaf(a.y, s0, d.y * s1)
             + fmaf(a.z, s0, d.z * s1) + fmaf(a.w, s0, d.w * s1);
    }
    float cum = loc;
#pragma unroll
    for (int st = 1; st < 32; st <<= 1) {
        float o = __shfl_up_sync(0xffffffffu, cum, st);
        if (lane >= st) cum += o;
    }
    unsigned m1 = __ballot_sync(0xffffffffu, cum > rn);
    int sel; float pv;
    const float* f0 = (const float*)c0;
    const float* f1 = (const float*)c1;
    if (m1 == 0u) {                          // never crossed (rn ~ 1): argmax of zeros = 0
        sel = 0;
        pv = f0[0] * s0 + f1[0] * s1;
    } else {
        int C = __ffs(m1) - 1;
        float run = (C == 0) ? 0.f : __shfl_sync(0xffffffffu, cum, C - 1);
        // pass 2: scan the 32 elements of chunk C
        int e = C * 32 + lane;
        float v = f0[e] * s0 + f1[e] * s1;
        float c2 = v;
#pragma unroll
        for (int st = 1; st < 32; st <<= 1) {
            float o = __shfl_up_sync(0xffffffffu, c2, st);
            if (lane >= st) c2 += o;
        }
        unsigned m2 = __ballot_sync(0xffffffffu, run + c2 > rn);
        int L = m2 ? (__ffs(m2) - 1) : 31;   // numeric-edge fallback: last element
        sel = C * 32 + L;
        pv = __shfl_sync(0xffffffffu, v, L);
    }
    if (lane == 0) {
        out[b] = (float)sel;
        out[BATCH + b] = logf(pv);
    }
}

// ---------------- launch: 5 kernels; slot 4 = k_scores (ncu capture slot) -------------
extern "C" void kernel_launch(void* const* d_in, const int* in_sizes, int n_in,
                              void* d_out, int out_size) {
    const float* x   = (const float*)d_in[0];  // [8192,384]
    const float* re  = (const float*)d_in[1];  // [1024,384]
    const float* rnd = (const float*)d_in[2];  // [8192,1]
    const float* gw  = (const float*)d_in[3];  // [384,8]
    const float* gb  = (const float*)d_in[4];  // [8]
    const float* Uw  = (const float*)d_in[5];  // [8,384,64]
    const float* Ub  = (const float*)d_in[6];  // [8,64]
    const float* Vw  = (const float*)d_in[7];  // [8,384,64]
    const float* Vb  = (const float*)d_in[8];  // [8,64]
    float* out = (float*)d_out;                // [0:8192]=idx, [8192:16384]=logp, [16384]=aux

    const int SCORES_SMEM = 4096 * 8 + 64 * 64 * 4;   // 49152 B
    cudaFuncSetAttribute(k_scores, cudaFuncAttributeMaxDynamicSharedMemorySize, SCORES_SMEM);

    k_ev        <<<RR * (EXP / TILE), 256>>>(re, Vw, Vb);      // 1: no deps
    k_gate      <<<BATCH / 8, 256>>>(x, gw, gb);               // 2: gate + scatter
    k_xu        <<<NBLK, 256>>>(x, Uw, Ub);                    // 3
    k_scores    <<<NBLK, 256, SCORES_SMEM>>>();                // 4  <- profiled
    k_select_aux<<<BATCH / 8 + 1, 256>>>(rnd, out);            // 5
}